// round 6
// baseline (speedup 1.0000x reference)
#include <cuda_runtime.h>
#include <cstdint>

// ---------------------------------------------------------------------------
// DialogueTransformer on GB300 (sm_103a, base sm_103 PTX => legacy mma.sync).
// R6: INT8 IMMA dual-quantization GEMMs.
//  x ~ s * (a1*128 + a0), a1,a0 int8  =>  A.B = sa*sb*(16384*P1 + 128*P23)
//  P1 = a1b1 ; P23 = a1b0 + a0b1 (shared accumulator). Exact int32 math.
// ---------------------------------------------------------------------------

#define MDIM 16384
#define DDIM 1024

__device__ __align__(256) float g_qkv[MDIM * 3 * DDIM];
__device__ __align__(256) float g_kv[MDIM * 2 * DDIM];
__device__ __align__(256) float g_t[MDIM * DDIM];
__device__ __align__(256) char  g_a1[MDIM * DDIM], g_a0[MDIM * DDIM];
__device__ __align__(256) char  g_e1[MDIM * DDIM], g_e0[MDIM * DDIM];
__device__ __align__(256) char  g_b1[3 * DDIM * DDIM], g_b0[3 * DDIM * DDIM];
__device__ __align__(256) float g_sa[MDIM], g_se[MDIM], g_sb[3 * DDIM];

// ---------------------------------------------------------------------------
// PTX helpers (baseline sm_80+ PTX only)
// ---------------------------------------------------------------------------
__device__ __forceinline__ uint32_t smem_to_u32(const void* p) {
    uint32_t a;
    asm("{ .reg .u64 t; cvta.to.shared.u64 t, %1; cvt.u32.u64 %0, t; }" : "=r"(a) : "l"(p));
    return a;
}
__device__ __forceinline__ void cp_async16(uint32_t saddr, const void* gptr) {
    asm volatile("cp.async.cg.shared.global [%0], [%1], 16;" :: "r"(saddr), "l"(gptr));
}
__device__ __forceinline__ void cp_commit() { asm volatile("cp.async.commit_group;"); }
__device__ __forceinline__ void cp_wait_all() { asm volatile("cp.async.wait_group 0;" ::: "memory"); }

__device__ __forceinline__ void ldsm_x4(uint32_t* r, uint32_t addr) {
    asm volatile("ldmatrix.sync.aligned.m8n8.x4.shared.b16 {%0,%1,%2,%3}, [%4];"
                 : "=r"(r[0]), "=r"(r[1]), "=r"(r[2]), "=r"(r[3]) : "r"(addr));
}
// int8 MMA: D(s32) += A(s8[16x32]) * B(s8[32x8])
__device__ __forceinline__ void imma16832(int* c, const uint32_t* a,
                                          uint32_t b0, uint32_t b1) {
    asm volatile(
        "mma.sync.aligned.m16n8k32.row.col.s32.s8.s8.s32 "
        "{%0,%1,%2,%3}, {%4,%5,%6,%7}, {%8,%9}, {%0,%1,%2,%3};"
        : "+r"(c[0]), "+r"(c[1]), "+r"(c[2]), "+r"(c[3])
        : "r"(a[0]), "r"(a[1]), "r"(a[2]), "r"(a[3]), "r"(b0), "r"(b1));
}

// quantize x/s into (q1, q0): q = q1*128 + q0, |q| <= 16256, |q0| <= 64
__device__ __forceinline__ void quant_pair(float x, float inv_s, int& q1, int& q0) {
    int q = __float2int_rn(x * inv_s);
    q = max(-16256, min(16256, q));
    int hi = ((q + 16448) >> 7) - 128;   // round-to-nearest-ish split
    q1 = hi;
    q0 = q - (hi << 7);
}

// ---------------------------------------------------------------------------
// INT8 GEMM: C[m,gn] = sa[m]*sb[gn]*(16384*P1 + 128*P23) + bias(gn)
// BM=128, BN=128, BK=64 (bytes), 256 thr, 8 warps (2x4 -> 64x32 warp tiles).
// ---------------------------------------------------------------------------
#define BM 128
#define BN 128
#define BK 64
#define NKB (DDIM / BK)   // 16
#define ROWB 80           // 64B payload + 16B pad (conflict-free ldsm)
#define TILE_BYTES (128 * ROWB)
#define STAGE_BYTES (4 * TILE_BYTES)     // A1,A0,B1,B0 = 40960
#define GEMM_SMEM (2 * STAGE_BYTES)      // 81920

template <bool RELU>
__global__ __launch_bounds__(256)
void gemm_i8(const char* __restrict__ A1g, const char* __restrict__ A0g,
             const float* __restrict__ SA,
             const char* __restrict__ B1g, const char* __restrict__ B0g,
             const float* __restrict__ SB,
             const float* __restrict__ b0, const float* __restrict__ b1,
             const float* __restrict__ b2,
             float* __restrict__ C, int ldc) {
    extern __shared__ char smem[];
    const uint32_t sb = smem_to_u32(smem);
    const int tid = threadIdx.x;
    const int wid = tid >> 5;
    const int lane = tid & 31;
    const int bm = blockIdx.y * BM;
    const int gn = blockIdx.x * BN;
    const int wm = (wid & 1) * 64;
    const int wn = (wid >> 1) * 32;

    auto OFF_A1 = [](int s) { return s * STAGE_BYTES + 0 * TILE_BYTES; };
    auto OFF_A0 = [](int s) { return s * STAGE_BYTES + 1 * TILE_BYTES; };
    auto OFF_B1 = [](int s) { return s * STAGE_BYTES + 2 * TILE_BYTES; };
    auto OFF_B0 = [](int s) { return s * STAGE_BYTES + 3 * TILE_BYTES; };

    // fill: 128 rows x 64B per matrix = 512 chunks; 2 chunks/thread/matrix
    const int fr = tid >> 1;
    const int fc0 = (tid & 1) * 2;
    const char* gA1 = A1g + (size_t)(bm + fr) * DDIM;
    const char* gA0 = A0g + (size_t)(bm + fr) * DDIM;
    const char* gB1 = B1g + (size_t)(gn + fr) * DDIM;
    const char* gB0 = B0g + (size_t)(gn + fr) * DDIM;

    auto fill_stage = [&](int s, int kb) {
        const int k0 = kb * BK;
        const uint32_t srow = fr * ROWB;
#pragma unroll
        for (int i = 0; i < 2; i++) {
            const int c = fc0 + i;
            const uint32_t so = srow + c * 16;
            const int go = k0 + c * 16;
            cp_async16(sb + OFF_A1(s) + so, gA1 + go);
            cp_async16(sb + OFF_A0(s) + so, gA0 + go);
            cp_async16(sb + OFF_B1(s) + so, gB1 + go);
            cp_async16(sb + OFF_B0(s) + so, gB0 + go);
        }
        cp_commit();
    };

    fill_stage(0, 0);
    cp_wait_all();
    __syncthreads();

    int P1[4][4][4], P23[4][4][4];
#pragma unroll
    for (int i = 0; i < 4; i++)
#pragma unroll
        for (int j = 0; j < 4; j++)
#pragma unroll
            for (int q = 0; q < 4; q++) { P1[i][j][q] = 0; P23[i][j][q] = 0; }

    const uint32_t lrow = (lane & 15);
    const uint32_t lcol = (lane >> 4) * 16;

    for (int kb = 0; kb < NKB; kb++) {
        const int s = kb & 1;
        if (kb + 1 < NKB) fill_stage(s ^ 1, kb + 1);

        const uint32_t a1b = sb + OFF_A1(s) + (wm + lrow) * ROWB + lcol;
        const uint32_t a0b = sb + OFF_A0(s) + (wm + lrow) * ROWB + lcol;
        const uint32_t b1b = sb + OFF_B1(s) + (wn + lrow) * ROWB + lcol;
        const uint32_t b0b = sb + OFF_B0(s) + (wn + lrow) * ROWB + lcol;

#pragma unroll
        for (int ks = 0; ks < 2; ks++) {
            const uint32_t ko = ks * 32;   // 32 bytes = k32 step
            uint32_t b1f[2][4], b0f[2][4];
#pragma unroll
            for (int p = 0; p < 2; p++) {
                ldsm_x4(b1f[p], b1b + p * (16 * ROWB) + ko);
                ldsm_x4(b0f[p], b0b + p * (16 * ROWB) + ko);
            }
#pragma unroll
            for (int mt = 0; mt < 4; mt++) {
                uint32_t a1f[4], a0f[4];
                ldsm_x4(a1f, a1b + mt * (16 * ROWB) + ko);
                ldsm_x4(a0f, a0b + mt * (16 * ROWB) + ko);
#pragma unroll
                for (int nt = 0; nt < 4; nt++) {
                    const int p = nt >> 1, o = nt & 1;
                    imma16832(P1[mt][nt],  a1f, b1f[p][o], b1f[p][o + 2]);
                    imma16832(P23[mt][nt], a1f, b0f[p][o], b0f[p][o + 2]);
                    imma16832(P23[mt][nt], a0f, b1f[p][o], b1f[p][o + 2]);
                }
            }
        }
        if (kb + 1 < NKB) cp_wait_all();
        __syncthreads();
    }

    // ---- epilogue ----
    const int g = lane >> 2, t4 = lane & 3;
    const float* bias = (blockIdx.x < 8) ? b0 : ((blockIdx.x < 16) ? b1 : b2);
    const int bb = (blockIdx.x & 7) * BN + wn;

#pragma unroll
    for (int mt = 0; mt < 4; mt++) {
        const int row0 = bm + wm + mt * 16 + g;
        const float sa0 = SA[row0];
        const float sa1 = SA[row0 + 8];
        float* p0 = C + (size_t)row0 * ldc + gn + wn;
        float* p1 = p0 + 8 * (size_t)ldc;
#pragma unroll
        for (int nt = 0; nt < 4; nt++) {
            const int col = nt * 8 + 2 * t4;
            const float sbx = SB[gn + wn + col];
            const float sby = SB[gn + wn + col + 1];
            const float bx = bias[bb + col];
            const float by = bias[bb + col + 1];
            float f0 = fmaf(16384.f, (float)P1[mt][nt][0], 128.f * (float)P23[mt][nt][0]);
            float f1 = fmaf(16384.f, (float)P1[mt][nt][1], 128.f * (float)P23[mt][nt][1]);
            float f2 = fmaf(16384.f, (float)P1[mt][nt][2], 128.f * (float)P23[mt][nt][2]);
            float f3 = fmaf(16384.f, (float)P1[mt][nt][3], 128.f * (float)P23[mt][nt][3]);
            float2 v0, v1;
            v0.x = fmaf(sa0 * sbx, f0, bx);
            v0.y = fmaf(sa0 * sby, f1, by);
            v1.x = fmaf(sa1 * sbx, f2, bx);
            v1.y = fmaf(sa1 * sby, f3, by);
            if (RELU) {
                v0.x = fmaxf(v0.x, 0.0f); v0.y = fmaxf(v0.y, 0.0f);
                v1.x = fmaxf(v1.x, 0.0f); v1.y = fmaxf(v1.y, 0.0f);
            }
            *(float2*)(p0 + col) = v0;
            *(float2*)(p1 + col) = v1;
        }
    }
}

// ---------------------------------------------------------------------------
// Quantizers: one block (256 thr) per row of 1024 floats.
// ---------------------------------------------------------------------------
template <bool PE>
__global__ __launch_bounds__(256)
void quant_act(const float* __restrict__ x, const float* __restrict__ pe,
               char* __restrict__ A1, char* __restrict__ A0,
               float* __restrict__ SA) {
    __shared__ float smax[8];
    const int row = blockIdx.x;
    const int t = threadIdx.x;
    float4 v = *(const float4*)(x + (size_t)row * DDIM + t * 4);
    if (PE) {
        const float4 p4 = *(const float4*)(pe + t * 4);
        v.x += p4.x; v.y += p4.y; v.z += p4.z; v.w += p4.w;
    }
    float mx = fmaxf(fmaxf(fabsf(v.x), fabsf(v.y)), fmaxf(fabsf(v.z), fabsf(v.w)));
#pragma unroll
    for (int o = 16; o; o >>= 1) mx = fmaxf(mx, __shfl_xor_sync(0xffffffffu, mx, o));
    if ((t & 31) == 0) smax[t >> 5] = mx;
    __syncthreads();
    mx = smax[0];
#pragma unroll
    for (int i = 1; i < 8; i++) mx = fmaxf(mx, smax[i]);
    const float inv = (mx > 1e-30f) ? 16256.0f / mx : 0.0f;
    if (t == 0) SA[row] = (mx > 1e-30f) ? mx / 16256.0f : 0.0f;
    int q1[4], q0[4];
    quant_pair(v.x, inv, q1[0], q0[0]);
    quant_pair(v.y, inv, q1[1], q0[1]);
    quant_pair(v.z, inv, q1[2], q0[2]);
    quant_pair(v.w, inv, q1[3], q0[3]);
    *(char4*)(A1 + (size_t)row * DDIM + t * 4) =
        make_char4((char)q1[0], (char)q1[1], (char)q1[2], (char)q1[3]);
    *(char4*)(A0 + (size_t)row * DDIM + t * 4) =
        make_char4((char)q0[0], (char)q0[1], (char)q0[2], (char)q0[3]);
}

// weights: up to 3 matrices concatenated along rows
__global__ __launch_bounds__(256)
void quant_w(const float* __restrict__ w0, const float* __restrict__ w1,
             const float* __restrict__ w2,
             char* __restrict__ B1, char* __restrict__ B0,
             float* __restrict__ SB) {
    __shared__ float smax[8];
    const int row = blockIdx.x;
    const int which = row >> 10;
    const float* src = (which == 0) ? w0 : ((which == 1) ? w1 : w2);
    const int r = row & 1023;
    const int t = threadIdx.x;
    float4 v = *(const float4*)(src + (size_t)r * DDIM + t * 4);
    float mx = fmaxf(fmaxf(fabsf(v.x), fabsf(v.y)), fmaxf(fabsf(v.z), fabsf(v.w)));
#pragma unroll
    for (int o = 16; o; o >>= 1) mx = fmaxf(mx, __shfl_xor_sync(0xffffffffu, mx, o));
    if ((t & 31) == 0) smax[t >> 5] = mx;
    __syncthreads();
    mx = smax[0];
#pragma unroll
    for (int i = 1; i < 8; i++) mx = fmaxf(mx, smax[i]);
    const float inv = (mx > 1e-30f) ? 16256.0f / mx : 0.0f;
    if (t == 0) SB[row] = (mx > 1e-30f) ? mx / 16256.0f : 0.0f;
    int q1[4], q0[4];
    quant_pair(v.x, inv, q1[0], q0[0]);
    quant_pair(v.y, inv, q1[1], q0[1]);
    quant_pair(v.z, inv, q1[2], q0[2]);
    quant_pair(v.w, inv, q1[3], q0[3]);
    *(char4*)(B1 + (size_t)row * DDIM + t * 4) =
        make_char4((char)q1[0], (char)q1[1], (char)q1[2], (char)q1[3]);
    *(char4*)(B0 + (size_t)row * DDIM + t * 4) =
        make_char4((char)q0[0], (char)q0[1], (char)q0[2], (char)q0[3]);
}

// ---------------------------------------------------------------------------
// Per-position 8x8 head-mix attention; fp32 in (strided), quantized out.
// ---------------------------------------------------------------------------
#define QROW 132

__global__ __launch_bounds__(128)
void attn_kernel(const float* __restrict__ Q, int qs,
                 const float* __restrict__ K, int ks_,
                 const float* __restrict__ V, int vs,
                 char* __restrict__ A1, char* __restrict__ A0,
                 float* __restrict__ SA) {
    __shared__ float sq[8 * QROW + 4];
    __shared__ float sk[8 * QROW + 4];
    __shared__ float sw[64];
    __shared__ float smax[4];

    const int p = blockIdx.x;
    const int t = threadIdx.x;
    const float* Qb = Q + (size_t)p * qs;
    const float* Kb = K + (size_t)p * ks_;
    const float* Vb = V + (size_t)p * vs;

#pragma unroll
    for (int u = 0; u < 2; u++) {
        const int e = (t + u * 128) * 4;
        const int i = e >> 7, h = e & 127;
        *(float4*)(sq + i * QROW + h) = *(const float4*)(Qb + e);
        *(float4*)(sk + i * QROW + h) = *(const float4*)(Kb + e);
    }
    __syncthreads();

    if (t < 64) {
        const int i = t >> 3, j = t & 7;
        const float* qi = &sq[i * QROW];
        const float* kj = &sk[j * QROW];
        float s = 0.0f;
#pragma unroll
        for (int h = 0; h < 128; h += 4) {
            const float4 a = *(const float4*)(qi + h);
            const float4 b = *(const float4*)(kj + h);
            s += a.x * b.x + a.y * b.y + a.z * b.z + a.w * b.w;
        }
        sw[t] = s * 0.08838834764831845f;
    }
    __syncthreads();

    if (t < 8) {
        float m = sw[t * 8];
#pragma unroll
        for (int j = 1; j < 8; j++) m = fmaxf(m, sw[t * 8 + j]);
        float s = 0.0f;
        float e[8];
#pragma unroll
        for (int j = 0; j < 8; j++) { e[j] = __expf(sw[t * 8 + j] - m); s += e[j]; }
        const float inv = 1.0f / s;
#pragma unroll
        for (int j = 0; j < 8; j++) sw[t * 8 + j] = e[j] * inv;
    }
    __syncthreads();

    float vj[8];
#pragma unroll
    for (int j = 0; j < 8; j++) vj[j] = Vb[j * 128 + t];
    float o[8];
    float mx = 0.0f;
#pragma unroll
    for (int i = 0; i < 8; i++) {
        float acc = 0.0f;
#pragma unroll
        for (int j = 0; j < 8; j++) acc += sw[i * 8 + j] * vj[j];
        o[i] = acc;
        mx = fmaxf(mx, fabsf(acc));
    }
    // block max over 128 threads
#pragma unroll
    for (int u = 16; u; u >>= 1) mx = fmaxf(mx, __shfl_xor_sync(0xffffffffu, mx, u));
    if ((t & 31) == 0) smax[t >> 5] = mx;
    __syncthreads();
    mx = fmaxf(fmaxf(smax[0], smax[1]), fmaxf(smax[2], smax[3]));
    const float inv = (mx > 1e-30f) ? 16256.0f / mx : 0.0f;
    if (t == 0) SA[p] = (mx > 1e-30f) ? mx / 16256.0f : 0.0f;

    const size_t obase = (size_t)p * 1024;
#pragma unroll
    for (int i = 0; i < 8; i++) {
        int q1, q0;
        quant_pair(o[i], inv, q1, q0);
        A1[obase + i * 128 + t] = (char)q1;
        A0[obase + i * 128 + t] = (char)q0;
    }
}

// ---------------------------------------------------------------------------
// Launch
// ---------------------------------------------------------------------------
extern "C" void kernel_launch(void* const* d_in, const int* in_sizes, int n_in,
                              void* d_out, int out_size) {
    const float* input_seq  = (const float*)d_in[0];
    const float* output_seq = (const float*)d_in[1];
    const float* pe         = (const float*)d_in[2];
    const float* enc_wq = (const float*)d_in[3];   const float* enc_bq = (const float*)d_in[4];
    const float* enc_wk = (const float*)d_in[5];   const float* enc_bk = (const float*)d_in[6];
    const float* enc_wv = (const float*)d_in[7];   const float* enc_bv = (const float*)d_in[8];
    const float* enc_w1 = (const float*)d_in[9];   const float* enc_b1 = (const float*)d_in[10];
    const float* enc_w2 = (const float*)d_in[11];  const float* enc_b2 = (const float*)d_in[12];
    const float* dec_s_wq = (const float*)d_in[13]; const float* dec_s_bq = (const float*)d_in[14];
    const float* dec_s_wk = (const float*)d_in[15]; const float* dec_s_bk = (const float*)d_in[16];
    const float* dec_s_wv = (const float*)d_in[17]; const float* dec_s_bv = (const float*)d_in[18];
    const float* dec_c_wq = (const float*)d_in[19]; const float* dec_c_bq = (const float*)d_in[20];
    const float* dec_c_wk = (const float*)d_in[21]; const float* dec_c_bk = (const float*)d_in[22];
    const float* dec_c_wv = (const float*)d_in[23]; const float* dec_c_bv = (const float*)d_in[24];
    const float* dec_w1 = (const float*)d_in[25];  const float* dec_b1 = (const float*)d_in[26];
    const float* dec_w2 = (const float*)d_in[27];  const float* dec_b2 = (const float*)d_in[28];
    const float* fc_w   = (const float*)d_in[29];  const float* fc_b   = (const float*)d_in[30];

    float *QKV, *KV, *T, *SA, *SE, *SB;
    char *A1, *A0, *E1, *E0, *B1, *B0;
    cudaGetSymbolAddress((void**)&QKV, g_qkv);
    cudaGetSymbolAddress((void**)&KV, g_kv);
    cudaGetSymbolAddress((void**)&T, g_t);
    cudaGetSymbolAddress((void**)&A1, g_a1);  cudaGetSymbolAddress((void**)&A0, g_a0);
    cudaGetSymbolAddress((void**)&E1, g_e1);  cudaGetSymbolAddress((void**)&E0, g_e0);
    cudaGetSymbolAddress((void**)&B1, g_b1);  cudaGetSymbolAddress((void**)&B0, g_b0);
    cudaGetSymbolAddress((void**)&SA, g_sa);  cudaGetSymbolAddress((void**)&SE, g_se);
    cudaGetSymbolAddress((void**)&SB, g_sb);
    float* OUT = (float*)d_out;

    cudaFuncSetAttribute(gemm_i8<false>, cudaFuncAttributeMaxDynamicSharedMemorySize, GEMM_SMEM);
    cudaFuncSetAttribute(gemm_i8<true>,  cudaFuncAttributeMaxDynamicSharedMemorySize, GEMM_SMEM);

    auto gemm = [&](int ng, const char* a1, const char* a0, const float* sa,
                    const float* bb0, const float* bb1, const float* bb2,
                    float* C, int ldc, bool relu) {
        if (relu)
            gemm_i8<true><<<dim3(ng * 8, MDIM / BM), 256, GEMM_SMEM>>>(
                a1, a0, sa, B1, B0, SB, bb0, bb1, bb2, C, ldc);
        else
            gemm_i8<false><<<dim3(ng * 8, MDIM / BM), 256, GEMM_SMEM>>>(
                a1, a0, sa, B1, B0, SB, bb0, bb1, bb2, C, ldc);
    };

    // ---- encoder ----
    quant_act<true><<<MDIM, 256>>>(input_seq, pe, A1, A0, SA);
    quant_w<<<3 * DDIM, 256>>>(enc_wq, enc_wk, enc_wv, B1, B0, SB);
    gemm(3, A1, A0, SA, enc_bq, enc_bk, enc_bv, QKV, 3 * DDIM, false);
    attn_kernel<<<MDIM, 128>>>(QKV, 3 * DDIM, QKV + DDIM, 3 * DDIM, QKV + 2 * DDIM, 3 * DDIM,
                               A1, A0, SA);
    quant_w<<<DDIM, 256>>>(enc_w1, enc_w1, enc_w1, B1, B0, SB);
    gemm(1, A1, A0, SA, enc_b1, enc_b1, enc_b1, T, DDIM, true);
    quant_act<false><<<MDIM, 256>>>(T, nullptr, A1, A0, SA);
    quant_w<<<DDIM, 256>>>(enc_w2, enc_w2, enc_w2, B1, B0, SB);
    gemm(1, A1, A0, SA, enc_b2, enc_b2, enc_b2, T, DDIM, false);
    quant_act<false><<<MDIM, 256>>>(T, nullptr, E1, E0, SE);   // enc_out -> E set

    // ---- decoder self-attn ----
    quant_act<false><<<MDIM, 256>>>(output_seq, nullptr, A1, A0, SA);
    quant_w<<<3 * DDIM, 256>>>(dec_s_wq, dec_s_wk, dec_s_wv, B1, B0, SB);
    gemm(3, A1, A0, SA, dec_s_bq, dec_s_bk, dec_s_bv, QKV, 3 * DDIM, false);
    attn_kernel<<<MDIM, 128>>>(QKV, 3 * DDIM, QKV + DDIM, 3 * DDIM, QKV + 2 * DDIM, 3 * DDIM,
                               A1, A0, SA);                    // sa -> A set

    // ---- decoder cross-attn ----
    quant_w<<<DDIM, 256>>>(dec_c_wq, dec_c_wq, dec_c_wq, B1, B0, SB);
    gemm(1, A1, A0, SA, dec_c_bq, dec_c_bq, dec_c_bq, T, DDIM, false);   // Q
    quant_w<<<2 * DDIM, 256>>>(dec_c_wk, dec_c_wv, dec_c_wv, B1, B0, SB);
    gemm(2, E1, E0, SE, dec_c_bk, dec_c_bv, dec_c_bv, KV, 2 * DDIM, false);  // K,V
    attn_kernel<<<MDIM, 128>>>(T, DDIM, KV, 2 * DDIM, KV + DDIM, 2 * DDIM,
                               A1, A0, SA);                    // ca -> A set

    // ---- decoder FFN + fc ----
    quant_w<<<DDIM, 256>>>(dec_w1, dec_w1, dec_w1, B1, B0, SB);
    gemm(1, A1, A0, SA, dec_b1, dec_b1, dec_b1, T, DDIM, true);
    quant_act<false><<<MDIM, 256>>>(T, nullptr, A1, A0, SA);
    quant_w<<<DDIM, 256>>>(dec_w2, dec_w2, dec_w2, B1, B0, SB);
    gemm(1, A1, A0, SA, dec_b2, dec_b2, dec_b2, T, DDIM, false);
    quant_act<false><<<MDIM, 256>>>(T, nullptr, A1, A0, SA);
    quant_w<<<DDIM, 256>>>(fc_w, fc_w, fc_w, B1, B0, SB);
    gemm(1, A1, A0, SA, fc_b, fc_b, fc_b, OUT, DDIM, false);
}

// round 7
// speedup vs baseline: 3.0818x; 3.0818x over previous
#include <cuda_runtime.h>
#include <cuda_fp16.h>
#include <cstdint>

// ---------------------------------------------------------------------------
// DialogueTransformer on GB300 (sm_103a, base sm_103 PTX => legacy mma.sync).
// R7: fp16 two-term GEMMs: C = a_h*(w_h + w_l), weights split exactly into an
// fp16 pair, activations single fp16. 2 HMMA products per GEMM (was 3 bf16).
// ---------------------------------------------------------------------------

#define MDIM 16384
#define DDIM 1024

__device__ __align__(256) float g_qkv[MDIM * 3 * DDIM];
__device__ __align__(256) float g_kv[MDIM * 2 * DDIM];
__device__ __align__(256) float g_tq[MDIM * DDIM];
__device__ __align__(256) __half g_xq[MDIM * DDIM];
__device__ __align__(256) __half g_aq[MDIM * DDIM];
__device__ __align__(256) __half g_pq[MDIM * DDIM];
__device__ __align__(256) __half g_eq[MDIM * DDIM];
__device__ __align__(256) __half g_wh[3 * DDIM * DDIM], g_wl[3 * DDIM * DDIM];

// ---------------------------------------------------------------------------
// PTX helpers (baseline sm_80+ PTX only)
// ---------------------------------------------------------------------------
__device__ __forceinline__ uint32_t smem_to_u32(const void* p) {
    uint32_t a;
    asm("{ .reg .u64 t; cvta.to.shared.u64 t, %1; cvt.u32.u64 %0, t; }" : "=r"(a) : "l"(p));
    return a;
}
__device__ __forceinline__ void cp_async16(uint32_t saddr, const void* gptr) {
    asm volatile("cp.async.cg.shared.global [%0], [%1], 16;" :: "r"(saddr), "l"(gptr));
}
__device__ __forceinline__ void cp_commit() { asm volatile("cp.async.commit_group;"); }
__device__ __forceinline__ void cp_wait_all() { asm volatile("cp.async.wait_group 0;" ::: "memory"); }

__device__ __forceinline__ void ldsm_x4(uint32_t* r, uint32_t addr) {
    asm volatile("ldmatrix.sync.aligned.m8n8.x4.shared.b16 {%0,%1,%2,%3}, [%4];"
                 : "=r"(r[0]), "=r"(r[1]), "=r"(r[2]), "=r"(r[3]) : "r"(addr));
}
__device__ __forceinline__ void mma16816(float* c, const uint32_t* a,
                                         uint32_t b0, uint32_t b1) {
    asm volatile(
        "mma.sync.aligned.m16n8k16.row.col.f32.f16.f16.f32 "
        "{%0,%1,%2,%3}, {%4,%5,%6,%7}, {%8,%9}, {%0,%1,%2,%3};"
        : "+f"(c[0]), "+f"(c[1]), "+f"(c[2]), "+f"(c[3])
        : "r"(a[0]), "r"(a[1]), "r"(a[2]), "r"(a[3]), "r"(b0), "r"(b1));
}

// ---------------------------------------------------------------------------
// fp16x2 GEMM: C[m,gn] = sum_k a[m,k]*(wh[gn,k]+wl[gn,k]) + bias(gn)
// BM=128, BN=128, BK=32 halves, 256 thr, 8 warps (2x4 -> 64x32 warp tiles).
// Output: fp32 (ldc) or fp16 (for chained GEMMs).
// ---------------------------------------------------------------------------
#define BM 128
#define BN 128
#define BK 32
#define NKB (DDIM / BK)   // 32
#define ROWB 80           // 64B payload + 16B pad (conflict-free ldsm)
#define TILE_BYTES (128 * ROWB)          // 10240
#define STAGE_BYTES (3 * TILE_BYTES)     // A, Wh, Wl = 30720
#define GEMM_SMEM (2 * STAGE_BYTES)      // 61440

template <bool RELU, bool F16OUT>
__global__ __launch_bounds__(256, 2)
void gemm_f16x2(const __half* __restrict__ Ag,
                const __half* __restrict__ WHg,
                const __half* __restrict__ WLg,
                const float* __restrict__ b0, const float* __restrict__ b1,
                const float* __restrict__ b2,
                float* __restrict__ Cf, __half* __restrict__ Ch, int ldc) {
    extern __shared__ char smem[];
    const uint32_t sb = smem_to_u32(smem);
    const int tid = threadIdx.x;
    const int wid = tid >> 5;
    const int lane = tid & 31;
    const int bm = blockIdx.y * BM;
    const int gn = blockIdx.x * BN;
    const int wm = (wid & 1) * 64;
    const int wn = (wid >> 1) * 32;

    auto OFF_A  = [](int s) { return s * STAGE_BYTES + 0 * TILE_BYTES; };
    auto OFF_WH = [](int s) { return s * STAGE_BYTES + 1 * TILE_BYTES; };
    auto OFF_WL = [](int s) { return s * STAGE_BYTES + 2 * TILE_BYTES; };

    // fill: 128 rows x 64B per matrix = 512 chunks of 16B; 2 per thread/matrix
    const int fr = tid >> 1;
    const int fc0 = (tid & 1) * 2;
    const __half* gA  = Ag  + (size_t)(bm + fr) * DDIM;
    const __half* gWH = WHg + (size_t)(gn + fr) * DDIM;
    const __half* gWL = WLg + (size_t)(gn + fr) * DDIM;

    auto fill_stage = [&](int s, int kb) {
        const int k0 = kb * BK;
        const uint32_t srow = fr * ROWB;
#pragma unroll
        for (int i = 0; i < 2; i++) {
            const int c = fc0 + i;
            const uint32_t so = srow + c * 16;
            const int go = k0 + c * 8;     // 8 halves = 16B
            cp_async16(sb + OFF_A(s)  + so, gA + go);
            cp_async16(sb + OFF_WH(s) + so, gWH + go);
            cp_async16(sb + OFF_WL(s) + so, gWL + go);
        }
        cp_commit();
    };

    fill_stage(0, 0);
    cp_wait_all();
    __syncthreads();

    float acc[4][4][4];
#pragma unroll
    for (int i = 0; i < 4; i++)
#pragma unroll
        for (int j = 0; j < 4; j++)
#pragma unroll
            for (int q = 0; q < 4; q++) acc[i][j][q] = 0.0f;

    const uint32_t lrow = (lane & 15);
    const uint32_t lcol = (lane >> 4) * 16;

    for (int kb = 0; kb < NKB; kb++) {
        const int s = kb & 1;
        if (kb + 1 < NKB) fill_stage(s ^ 1, kb + 1);

        const uint32_t ab  = sb + OFF_A(s)  + (wm + lrow) * ROWB + lcol;
        const uint32_t whb = sb + OFF_WH(s) + (wn + lrow) * ROWB + lcol;
        const uint32_t wlb = sb + OFF_WL(s) + (wn + lrow) * ROWB + lcol;

#pragma unroll
        for (int ks = 0; ks < 2; ks++) {
            const uint32_t ko = ks * 32;   // 16 halves = 32B
            uint32_t bh[2][4], bl[2][4];
#pragma unroll
            for (int p = 0; p < 2; p++) {
                ldsm_x4(bh[p], whb + p * (16 * ROWB) + ko);
                ldsm_x4(bl[p], wlb + p * (16 * ROWB) + ko);
            }
#pragma unroll
            for (int mt = 0; mt < 4; mt++) {
                uint32_t af[4];
                ldsm_x4(af, ab + mt * (16 * ROWB) + ko);
#pragma unroll
                for (int nt = 0; nt < 4; nt++) {
                    const int p = nt >> 1, o = nt & 1;
                    mma16816(acc[mt][nt], af, bh[p][o], bh[p][o + 2]);
                    mma16816(acc[mt][nt], af, bl[p][o], bl[p][o + 2]);
                }
            }
        }
        if (kb + 1 < NKB) cp_wait_all();
        __syncthreads();
    }

    // ---- epilogue ----
    const int g = lane >> 2, t4 = lane & 3;
    const float* bias = (blockIdx.x < 8) ? b0 : ((blockIdx.x < 16) ? b1 : b2);
    const int bb = (blockIdx.x & 7) * BN + wn;

#pragma unroll
    for (int mt = 0; mt < 4; mt++) {
        const int row0 = bm + wm + mt * 16 + g;
#pragma unroll
        for (int nt = 0; nt < 4; nt++) {
            const int col = nt * 8 + 2 * t4;
            const float bx = bias[bb + col];
            const float by = bias[bb + col + 1];
            float2 v0, v1;
            v0.x = acc[mt][nt][0] + bx;
            v0.y = acc[mt][nt][1] + by;
            v1.x = acc[mt][nt][2] + bx;
            v1.y = acc[mt][nt][3] + by;
            if (RELU) {
                v0.x = fmaxf(v0.x, 0.0f); v0.y = fmaxf(v0.y, 0.0f);
                v1.x = fmaxf(v1.x, 0.0f); v1.y = fmaxf(v1.y, 0.0f);
            }
            if (F16OUT) {
                const size_t o0 = (size_t)row0 * DDIM + gn + wn + col;
                *(__half2*)(Ch + o0) = __floats2half2_rn(v0.x, v0.y);
                *(__half2*)(Ch + o0 + 8 * DDIM) = __floats2half2_rn(v1.x, v1.y);
            } else {
                const size_t o0 = (size_t)row0 * ldc + gn + wn + col;
                *(float2*)(Cf + o0) = v0;
                *(float2*)(Cf + o0 + 8 * (size_t)ldc) = v1;
            }
        }
    }
}

// ---------------------------------------------------------------------------
// Converters
// ---------------------------------------------------------------------------
template <bool PE>
__global__ __launch_bounds__(256)
void conv_act(const float* __restrict__ x, const float* __restrict__ pe,
              __half* __restrict__ out) {
    const size_t i = ((size_t)blockIdx.x * 256 + threadIdx.x) * 4;
    float4 v = *(const float4*)(x + i);
    if (PE) {
        const int d = (int)(i & (DDIM - 1));
        v.x += pe[d + 0]; v.y += pe[d + 1]; v.z += pe[d + 2]; v.w += pe[d + 3];
    }
    __half2 h01 = __floats2half2_rn(v.x, v.y);
    __half2 h23 = __floats2half2_rn(v.z, v.w);
    *(uint2*)(out + i) = make_uint2(*(uint32_t*)&h01, *(uint32_t*)&h23);
}

// weights: up to 3 matrices concatenated along rows, exact fp16 pair
__global__ __launch_bounds__(256)
void conv_w(const float* __restrict__ w0, const float* __restrict__ w1,
            const float* __restrict__ w2,
            __half* __restrict__ WH, __half* __restrict__ WL) {
    const size_t i = ((size_t)blockIdx.x * 256 + threadIdx.x) * 4;
    const int which = (int)(i >> 20);
    const float* src = (which == 0) ? w0 : ((which == 1) ? w1 : w2);
    float4 v = *(const float4*)(src + (i & ((1u << 20) - 1)));
    __half h0 = __float2half_rn(v.x);
    __half h1 = __float2half_rn(v.y);
    __half h2 = __float2half_rn(v.z);
    __half h3 = __float2half_rn(v.w);
    __half l0 = __float2half_rn(v.x - __half2float(h0));
    __half l1 = __float2half_rn(v.y - __half2float(h1));
    __half l2 = __float2half_rn(v.z - __half2float(h2));
    __half l3 = __float2half_rn(v.w - __half2float(h3));
    __half2 H01 = __halves2half2(h0, h1), H23 = __halves2half2(h2, h3);
    __half2 L01 = __halves2half2(l0, l1), L23 = __halves2half2(l2, l3);
    *(uint2*)(WH + i) = make_uint2(*(uint32_t*)&H01, *(uint32_t*)&H23);
    *(uint2*)(WL + i) = make_uint2(*(uint32_t*)&L01, *(uint32_t*)&L23);
}

// ---------------------------------------------------------------------------
// Per-position 8x8 head-mix attention; fp32 strided in, fp16 out.
// ---------------------------------------------------------------------------
#define QROW 132

__global__ __launch_bounds__(128)
void attn_kernel(const float* __restrict__ Q, int qs,
                 const float* __restrict__ K, int ks_,
                 const float* __restrict__ V, int vs,
                 __half* __restrict__ O) {
    __shared__ float sq[8 * QROW + 4];
    __shared__ float sk[8 * QROW + 4];
    __shared__ float sw[64];

    const int p = blockIdx.x;
    const int t = threadIdx.x;
    const float* Qb = Q + (size_t)p * qs;
    const float* Kb = K + (size_t)p * ks_;
    const float* Vb = V + (size_t)p * vs;

#pragma unroll
    for (int u = 0; u < 2; u++) {
        const int e = (t + u * 128) * 4;
        const int i = e >> 7, h = e & 127;
        *(float4*)(sq + i * QROW + h) = *(const float4*)(Qb + e);
        *(float4*)(sk + i * QROW + h) = *(const float4*)(Kb + e);
    }
    __syncthreads();

    if (t < 64) {
        const int i = t >> 3, j = t & 7;
        const float* qi = &sq[i * QROW];
        const float* kj = &sk[j * QROW];
        float s = 0.0f;
#pragma unroll
        for (int h = 0; h < 128; h += 4) {
            const float4 a = *(const float4*)(qi + h);
            const float4 b = *(const float4*)(kj + h);
            s += a.x * b.x + a.y * b.y + a.z * b.z + a.w * b.w;
        }
        sw[t] = s * 0.08838834764831845f;
    }
    __syncthreads();

    if (t < 8) {
        float m = sw[t * 8];
#pragma unroll
        for (int j = 1; j < 8; j++) m = fmaxf(m, sw[t * 8 + j]);
        float s = 0.0f;
        float e[8];
#pragma unroll
        for (int j = 0; j < 8; j++) { e[j] = __expf(sw[t * 8 + j] - m); s += e[j]; }
        const float inv = 1.0f / s;
#pragma unroll
        for (int j = 0; j < 8; j++) sw[t * 8 + j] = e[j] * inv;
    }
    __syncthreads();

    float vj[8];
#pragma unroll
    for (int j = 0; j < 8; j++) vj[j] = Vb[j * 128 + t];
    const size_t obase = (size_t)p * 1024;
#pragma unroll
    for (int i = 0; i < 8; i++) {
        float o = 0.0f;
#pragma unroll
        for (int j = 0; j < 8; j++) o += sw[i * 8 + j] * vj[j];
        O[obase + i * 128 + t] = __float2half_rn(o);
    }
}

// ---------------------------------------------------------------------------
// Launch
// ---------------------------------------------------------------------------
extern "C" void kernel_launch(void* const* d_in, const int* in_sizes, int n_in,
                              void* d_out, int out_size) {
    const float* input_seq  = (const float*)d_in[0];
    const float* output_seq = (const float*)d_in[1];
    const float* pe         = (const float*)d_in[2];
    const float* enc_wq = (const float*)d_in[3];   const float* enc_bq = (const float*)d_in[4];
    const float* enc_wk = (const float*)d_in[5];   const float* enc_bk = (const float*)d_in[6];
    const float* enc_wv = (const float*)d_in[7];   const float* enc_bv = (const float*)d_in[8];
    const float* enc_w1 = (const float*)d_in[9];   const float* enc_b1 = (const float*)d_in[10];
    const float* enc_w2 = (const float*)d_in[11];  const float* enc_b2 = (const float*)d_in[12];
    const float* dec_s_wq = (const float*)d_in[13]; const float* dec_s_bq = (const float*)d_in[14];
    const float* dec_s_wk = (const float*)d_in[15]; const float* dec_s_bk = (const float*)d_in[16];
    const float* dec_s_wv = (const float*)d_in[17]; const float* dec_s_bv = (const float*)d_in[18];
    const float* dec_c_wq = (const float*)d_in[19]; const float* dec_c_bq = (const float*)d_in[20];
    const float* dec_c_wk = (const float*)d_in[21]; const float* dec_c_bk = (const float*)d_in[22];
    const float* dec_c_wv = (const float*)d_in[23]; const float* dec_c_bv = (const float*)d_in[24];
    const float* dec_w1 = (const float*)d_in[25];  const float* dec_b1 = (const float*)d_in[26];
    const float* dec_w2 = (const float*)d_in[27];  const float* dec_b2 = (const float*)d_in[28];
    const float* fc_w   = (const float*)d_in[29];  const float* fc_b   = (const float*)d_in[30];

    float *QKV, *KV, *T;
    __half *Xq, *Aq, *Pq, *Eq, *WH, *WL;
    cudaGetSymbolAddress((void**)&QKV, g_qkv);
    cudaGetSymbolAddress((void**)&KV, g_kv);
    cudaGetSymbolAddress((void**)&T, g_tq);
    cudaGetSymbolAddress((void**)&Xq, g_xq);
    cudaGetSymbolAddress((void**)&Aq, g_aq);
    cudaGetSymbolAddress((void**)&Pq, g_pq);
    cudaGetSymbolAddress((void**)&Eq, g_eq);
    cudaGetSymbolAddress((void**)&WH, g_wh);
    cudaGetSymbolAddress((void**)&WL, g_wl);
    float* OUT = (float*)d_out;

    cudaFuncSetAttribute(gemm_f16x2<false,false>, cudaFuncAttributeMaxDynamicSharedMemorySize, GEMM_SMEM);
    cudaFuncSetAttribute(gemm_f16x2<false,true>,  cudaFuncAttributeMaxDynamicSharedMemorySize, GEMM_SMEM);
    cudaFuncSetAttribute(gemm_f16x2<true,true>,   cudaFuncAttributeMaxDynamicSharedMemorySize, GEMM_SMEM);

    const int CA_BLK = MDIM * DDIM / (4 * 256);
    const int CW1 = DDIM * DDIM / (4 * 256);

    auto gemmF = [&](int ng, const __half* a,
                     const float* bb0, const float* bb1, const float* bb2,
                     float* C, int ldc) {
        gemm_f16x2<false,false><<<dim3(ng * 8, MDIM / BM), 256, GEMM_SMEM>>>(
            a, WH, WL, bb0, bb1, bb2, C, nullptr, ldc);
    };
    auto gemmH = [&](const __half* a, const float* bb, __half* C, bool relu) {
        if (relu)
            gemm_f16x2<true,true><<<dim3(8, MDIM / BM), 256, GEMM_SMEM>>>(
                a, WH, WL, bb, bb, bb, nullptr, C, DDIM);
        else
            gemm_f16x2<false,true><<<dim3(8, MDIM / BM), 256, GEMM_SMEM>>>(
                a, WH, WL, bb, bb, bb, nullptr, C, DDIM);
    };

    // ---- encoder ----
    conv_act<true><<<CA_BLK, 256>>>(input_seq, pe, Xq);
    conv_w<<<3 * CW1, 256>>>(enc_wq, enc_wk, enc_wv, WH, WL);
    gemmF(3, Xq, enc_bq, enc_bk, enc_bv, QKV, 3 * DDIM);
    attn_kernel<<<MDIM, 128>>>(QKV, 3 * DDIM, QKV + DDIM, 3 * DDIM, QKV + 2 * DDIM, 3 * DDIM, Aq);
    conv_w<<<CW1, 256>>>(enc_w1, enc_w1, enc_w1, WH, WL);
    gemmH(Aq, enc_b1, Pq, true);
    conv_w<<<CW1, 256>>>(enc_w2, enc_w2, enc_w2, WH, WL);
    gemmH(Pq, enc_b2, Eq, false);                 // enc_out (fp16)

    // ---- decoder self-attn ----
    conv_act<false><<<CA_BLK, 256>>>(output_seq, nullptr, Xq);
    conv_w<<<3 * CW1, 256>>>(dec_s_wq, dec_s_wk, dec_s_wv, WH, WL);
    gemmF(3, Xq, dec_s_bq, dec_s_bk, dec_s_bv, QKV, 3 * DDIM);
    attn_kernel<<<MDIM, 128>>>(QKV, 3 * DDIM, QKV + DDIM, 3 * DDIM, QKV + 2 * DDIM, 3 * DDIM, Aq);

    // ---- decoder cross-attn ----
    conv_w<<<CW1, 256>>>(dec_c_wq, dec_c_wq, dec_c_wq, WH, WL);
    gemmF(1, Aq, dec_c_bq, dec_c_bq, dec_c_bq, T, DDIM);          // Q (fp32)
    conv_w<<<2 * CW1, 256>>>(dec_c_wk, dec_c_wv, dec_c_wv, WH, WL);
    gemmF(2, Eq, dec_c_bk, dec_c_bv, dec_c_bv, KV, 2 * DDIM);     // K,V (fp32)
    attn_kernel<<<MDIM, 128>>>(T, DDIM, KV, 2 * DDIM, KV + DDIM, 2 * DDIM, Aq);

    // ---- decoder FFN + fc ----
    conv_w<<<CW1, 256>>>(dec_w1, dec_w1, dec_w1, WH, WL);
    gemmH(Aq, dec_b1, Pq, true);
    conv_w<<<CW1, 256>>>(dec_w2, dec_w2, dec_w2, WH, WL);
    gemmH(Pq, dec_b2, Xq, false);
    conv_w<<<CW1, 256>>>(fc_w, fc_w, fc_w, WH, WL);
    gemmF(1, Xq, fc_b, fc_b, fc_b, OUT, DDIM);
}

// round 8
// speedup vs baseline: 5.0317x; 1.6327x over previous
#include <cuda_runtime.h>
#include <cuda_fp16.h>
#include <cstdint>

// ---------------------------------------------------------------------------
// DialogueTransformer on GB300 (sm_103a, base sm_103 PTX => legacy mma.sync).
// R8: single-product fp16 HMMA GEMMs (weights and activations both rounded to
// one fp16). Calibrated chain rel_err ~3e-4 vs 1e-3 threshold.
// ---------------------------------------------------------------------------

#define MDIM 16384
#define DDIM 1024

__device__ __align__(256) float g_qkv[MDIM * 3 * DDIM];
__device__ __align__(256) float g_kv[MDIM * 2 * DDIM];
__device__ __align__(256) float g_tq[MDIM * DDIM];
__device__ __align__(256) __half g_xq[MDIM * DDIM];
__device__ __align__(256) __half g_aq[MDIM * DDIM];
__device__ __align__(256) __half g_pq[MDIM * DDIM];
__device__ __align__(256) __half g_eq[MDIM * DDIM];
__device__ __align__(256) __half g_wh[3 * DDIM * DDIM];

// ---------------------------------------------------------------------------
// PTX helpers (baseline sm_80+ PTX only)
// ---------------------------------------------------------------------------
__device__ __forceinline__ uint32_t smem_to_u32(const void* p) {
    uint32_t a;
    asm("{ .reg .u64 t; cvta.to.shared.u64 t, %1; cvt.u32.u64 %0, t; }" : "=r"(a) : "l"(p));
    return a;
}
__device__ __forceinline__ void cp_async16(uint32_t saddr, const void* gptr) {
    asm volatile("cp.async.cg.shared.global [%0], [%1], 16;" :: "r"(saddr), "l"(gptr));
}
__device__ __forceinline__ void cp_commit() { asm volatile("cp.async.commit_group;"); }
__device__ __forceinline__ void cp_wait_all() { asm volatile("cp.async.wait_group 0;" ::: "memory"); }

__device__ __forceinline__ void ldsm_x4(uint32_t* r, uint32_t addr) {
    asm volatile("ldmatrix.sync.aligned.m8n8.x4.shared.b16 {%0,%1,%2,%3}, [%4];"
                 : "=r"(r[0]), "=r"(r[1]), "=r"(r[2]), "=r"(r[3]) : "r"(addr));
}
__device__ __forceinline__ void mma16816(float* c, const uint32_t* a,
                                         uint32_t b0, uint32_t b1) {
    asm volatile(
        "mma.sync.aligned.m16n8k16.row.col.f32.f16.f16.f32 "
        "{%0,%1,%2,%3}, {%4,%5,%6,%7}, {%8,%9}, {%0,%1,%2,%3};"
        : "+f"(c[0]), "+f"(c[1]), "+f"(c[2]), "+f"(c[3])
        : "r"(a[0]), "r"(a[1]), "r"(a[2]), "r"(a[3]), "r"(b0), "r"(b1));
}

// ---------------------------------------------------------------------------
// fp16 GEMM: C[m,gn] = sum_k a[m,k]*w[gn,k] + bias(gn)
// BM=128, BN=128, BK=32 halves, 256 thr, 8 warps (2x4 -> 64x32 warp tiles).
// ---------------------------------------------------------------------------
#define BM 128
#define BN 128
#define BK 32
#define NKB (DDIM / BK)   // 32
#define ROWB 80
#define TILE_BYTES (128 * ROWB)          // 10240
#define STAGE_BYTES (2 * TILE_BYTES)     // A, W = 20480
#define GEMM_SMEM (2 * STAGE_BYTES)      // 40960

template <bool RELU, bool F16OUT>
__global__ __launch_bounds__(256, 2)
void gemm_f16(const __half* __restrict__ Ag,
              const __half* __restrict__ Wg,
              const float* __restrict__ b0, const float* __restrict__ b1,
              const float* __restrict__ b2,
              float* __restrict__ Cf, __half* __restrict__ Ch, int ldc) {
    extern __shared__ char smem[];
    const uint32_t sb = smem_to_u32(smem);
    const int tid = threadIdx.x;
    const int wid = tid >> 5;
    const int lane = tid & 31;
    const int bm = blockIdx.y * BM;
    const int gn = blockIdx.x * BN;
    const int wm = (wid & 1) * 64;
    const int wn = (wid >> 1) * 32;

    auto OFF_A = [](int s) { return s * STAGE_BYTES + 0 * TILE_BYTES; };
    auto OFF_W = [](int s) { return s * STAGE_BYTES + 1 * TILE_BYTES; };

    const int fr = tid >> 1;
    const int fc0 = (tid & 1) * 2;
    const __half* gA = Ag + (size_t)(bm + fr) * DDIM;
    const __half* gW = Wg + (size_t)(gn + fr) * DDIM;

    auto fill_stage = [&](int s, int kb) {
        const int k0 = kb * BK;
        const uint32_t srow = fr * ROWB;
#pragma unroll
        for (int i = 0; i < 2; i++) {
            const int c = fc0 + i;
            const uint32_t so = srow + c * 16;
            const int go = k0 + c * 8;
            cp_async16(sb + OFF_A(s) + so, gA + go);
            cp_async16(sb + OFF_W(s) + so, gW + go);
        }
        cp_commit();
    };

    fill_stage(0, 0);
    cp_wait_all();
    __syncthreads();

    float acc[4][4][4];
#pragma unroll
    for (int i = 0; i < 4; i++)
#pragma unroll
        for (int j = 0; j < 4; j++)
#pragma unroll
            for (int q = 0; q < 4; q++) acc[i][j][q] = 0.0f;

    const uint32_t lrow = (lane & 15);
    const uint32_t lcol = (lane >> 4) * 16;

    for (int kb = 0; kb < NKB; kb++) {
        const int s = kb & 1;
        if (kb + 1 < NKB) fill_stage(s ^ 1, kb + 1);

        const uint32_t ab = sb + OFF_A(s) + (wm + lrow) * ROWB + lcol;
        const uint32_t wb = sb + OFF_W(s) + (wn + lrow) * ROWB + lcol;

#pragma unroll
        for (int ks = 0; ks < 2; ks++) {
            const uint32_t ko = ks * 32;
            uint32_t bf[2][4];
#pragma unroll
            for (int p = 0; p < 2; p++)
                ldsm_x4(bf[p], wb + p * (16 * ROWB) + ko);
#pragma unroll
            for (int mt = 0; mt < 4; mt++) {
                uint32_t af[4];
                ldsm_x4(af, ab + mt * (16 * ROWB) + ko);
#pragma unroll
                for (int nt = 0; nt < 4; nt++) {
                    const int p = nt >> 1, o = nt & 1;
                    mma16816(acc[mt][nt], af, bf[p][o], bf[p][o + 2]);
                }
            }
        }
        if (kb + 1 < NKB) cp_wait_all();
        __syncthreads();
    }

    // ---- epilogue ----
    const int g = lane >> 2, t4 = lane & 3;
    const float* bias = (blockIdx.x < 8) ? b0 : ((blockIdx.x < 16) ? b1 : b2);
    const int bb = (blockIdx.x & 7) * BN + wn;

#pragma unroll
    for (int mt = 0; mt < 4; mt++) {
        const int row0 = bm + wm + mt * 16 + g;
#pragma unroll
        for (int nt = 0; nt < 4; nt++) {
            const int col = nt * 8 + 2 * t4;
            const float bx = bias[bb + col];
            const float by = bias[bb + col + 1];
            float2 v0, v1;
            v0.x = acc[mt][nt][0] + bx;
            v0.y = acc[mt][nt][1] + by;
            v1.x = acc[mt][nt][2] + bx;
            v1.y = acc[mt][nt][3] + by;
            if (RELU) {
                v0.x = fmaxf(v0.x, 0.0f); v0.y = fmaxf(v0.y, 0.0f);
                v1.x = fmaxf(v1.x, 0.0f); v1.y = fmaxf(v1.y, 0.0f);
            }
            if (F16OUT) {
                const size_t o0 = (size_t)row0 * DDIM + gn + wn + col;
                *(__half2*)(Ch + o0) = __floats2half2_rn(v0.x, v0.y);
                *(__half2*)(Ch + o0 + 8 * DDIM) = __floats2half2_rn(v1.x, v1.y);
            } else {
                const size_t o0 = (size_t)row0 * ldc + gn + wn + col;
                *(float2*)(Cf + o0) = v0;
                *(float2*)(Cf + o0 + 8 * (size_t)ldc) = v1;
            }
        }
    }
}

// ---------------------------------------------------------------------------
// Converters
// ---------------------------------------------------------------------------
template <bool PE>
__global__ __launch_bounds__(256)
void conv_act(const float* __restrict__ x, const float* __restrict__ pe,
              __half* __restrict__ out) {
    const size_t i = ((size_t)blockIdx.x * 256 + threadIdx.x) * 4;
    float4 v = *(const float4*)(x + i);
    if (PE) {
        const int d = (int)(i & (DDIM - 1));
        v.x += pe[d + 0]; v.y += pe[d + 1]; v.z += pe[d + 2]; v.w += pe[d + 3];
    }
    __half2 h01 = __floats2half2_rn(v.x, v.y);
    __half2 h23 = __floats2half2_rn(v.z, v.w);
    *(uint2*)(out + i) = make_uint2(*(uint32_t*)&h01, *(uint32_t*)&h23);
}

__global__ __launch_bounds__(256)
void conv_w(const float* __restrict__ w0, const float* __restrict__ w1,
            const float* __restrict__ w2, __half* __restrict__ WH) {
    const size_t i = ((size_t)blockIdx.x * 256 + threadIdx.x) * 4;
    const int which = (int)(i >> 20);
    const float* src = (which == 0) ? w0 : ((which == 1) ? w1 : w2);
    float4 v = *(const float4*)(src + (i & ((1u << 20) - 1)));
    __half2 h01 = __floats2half2_rn(v.x, v.y);
    __half2 h23 = __floats2half2_rn(v.z, v.w);
    *(uint2*)(WH + i) = make_uint2(*(uint32_t*)&h01, *(uint32_t*)&h23);
}

// ---------------------------------------------------------------------------
// Per-position 8x8 head-mix attention; fp32 strided in, fp16 out.
// ---------------------------------------------------------------------------
#define QROW 132

__global__ __launch_bounds__(128)
void attn_kernel(const float* __restrict__ Q, int qs,
                 const float* __restrict__ K, int ks_,
                 const float* __restrict__ V, int vs,
                 __half* __restrict__ O) {
    __shared__ float sq[8 * QROW + 4];
    __shared__ float sk[8 * QROW + 4];
    __shared__ float sw[64];

    const int p = blockIdx.x;
    const int t = threadIdx.x;
    const float* Qb = Q + (size_t)p * qs;
    const float* Kb = K + (size_t)p * ks_;
    const float* Vb = V + (size_t)p * vs;

#pragma unroll
    for (int u = 0; u < 2; u++) {
        const int e = (t + u * 128) * 4;
        const int i = e >> 7, h = e & 127;
        *(float4*)(sq + i * QROW + h) = *(const float4*)(Qb + e);
        *(float4*)(sk + i * QROW + h) = *(const float4*)(Kb + e);
    }
    __syncthreads();

    if (t < 64) {
        const int i = t >> 3, j = t & 7;
        const float* qi = &sq[i * QROW];
        const float* kj = &sk[j * QROW];
        float s = 0.0f;
#pragma unroll
        for (int h = 0; h < 128; h += 4) {
            const float4 a = *(const float4*)(qi + h);
            const float4 b = *(const float4*)(kj + h);
            s += a.x * b.x + a.y * b.y + a.z * b.z + a.w * b.w;
        }
        sw[t] = s * 0.08838834764831845f;
    }
    __syncthreads();

    if (t < 8) {
        float m = sw[t * 8];
#pragma unroll
        for (int j = 1; j < 8; j++) m = fmaxf(m, sw[t * 8 + j]);
        float s = 0.0f;
        float e[8];
#pragma unroll
        for (int j = 0; j < 8; j++) { e[j] = __expf(sw[t * 8 + j] - m); s += e[j]; }
        const float inv = 1.0f / s;
#pragma unroll
        for (int j = 0; j < 8; j++) sw[t * 8 + j] = e[j] * inv;
    }
    __syncthreads();

    float vj[8];
#pragma unroll
    for (int j = 0; j < 8; j++) vj[j] = Vb[j * 128 + t];
    const size_t obase = (size_t)p * 1024;
#pragma unroll
    for (int i = 0; i < 8; i++) {
        float o = 0.0f;
#pragma unroll
        for (int j = 0; j < 8; j++) o += sw[i * 8 + j] * vj[j];
        O[obase + i * 128 + t] = __float2half_rn(o);
    }
}

// ---------------------------------------------------------------------------
// Launch
// ---------------------------------------------------------------------------
extern "C" void kernel_launch(void* const* d_in, const int* in_sizes, int n_in,
                              void* d_out, int out_size) {
    const float* input_seq  = (const float*)d_in[0];
    const float* output_seq = (const float*)d_in[1];
    const float* pe         = (const float*)d_in[2];
    const float* enc_wq = (const float*)d_in[3];   const float* enc_bq = (const float*)d_in[4];
    const float* enc_wk = (const float*)d_in[5];   const float* enc_bk = (const float*)d_in[6];
    const float* enc_wv = (const float*)d_in[7];   const float* enc_bv = (const float*)d_in[8];
    const float* enc_w1 = (const float*)d_in[9];   const float* enc_b1 = (const float*)d_in[10];
    const float* enc_w2 = (const float*)d_in[11];  const float* enc_b2 = (const float*)d_in[12];
    const float* dec_s_wq = (const float*)d_in[13]; const float* dec_s_bq = (const float*)d_in[14];
    const float* dec_s_wk = (const float*)d_in[15]; const float* dec_s_bk = (const float*)d_in[16];
    const float* dec_s_wv = (const float*)d_in[17]; const float* dec_s_bv = (const float*)d_in[18];
    const float* dec_c_wq = (const float*)d_in[19]; const float* dec_c_bq = (const float*)d_in[20];
    const float* dec_c_wk = (const float*)d_in[21]; const float* dec_c_bk = (const float*)d_in[22];
    const float* dec_c_wv = (const float*)d_in[23]; const float* dec_c_bv = (const float*)d_in[24];
    const float* dec_w1 = (const float*)d_in[25];  const float* dec_b1 = (const float*)d_in[26];
    const float* dec_w2 = (const float*)d_in[27];  const float* dec_b2 = (const float*)d_in[28];
    const float* fc_w   = (const float*)d_in[29];  const float* fc_b   = (const float*)d_in[30];

    float *QKV, *KV, *T;
    __half *Xq, *Aq, *Pq, *Eq, *WH;
    cudaGetSymbolAddress((void**)&QKV, g_qkv);
    cudaGetSymbolAddress((void**)&KV, g_kv);
    cudaGetSymbolAddress((void**)&T, g_tq);
    cudaGetSymbolAddress((void**)&Xq, g_xq);
    cudaGetSymbolAddress((void**)&Aq, g_aq);
    cudaGetSymbolAddress((void**)&Pq, g_pq);
    cudaGetSymbolAddress((void**)&Eq, g_eq);
    cudaGetSymbolAddress((void**)&WH, g_wh);
    float* OUT = (float*)d_out;

    cudaFuncSetAttribute(gemm_f16<false,false>, cudaFuncAttributeMaxDynamicSharedMemorySize, GEMM_SMEM);
    cudaFuncSetAttribute(gemm_f16<false,true>,  cudaFuncAttributeMaxDynamicSharedMemorySize, GEMM_SMEM);
    cudaFuncSetAttribute(gemm_f16<true,true>,   cudaFuncAttributeMaxDynamicSharedMemorySize, GEMM_SMEM);

    const int CA_BLK = MDIM * DDIM / (4 * 256);
    const int CW1 = DDIM * DDIM / (4 * 256);

    auto gemmF = [&](int ng, const __half* a,
                     const float* bb0, const float* bb1, const float* bb2,
                     float* C, int ldc) {
        gemm_f16<false,false><<<dim3(ng * 8, MDIM / BM), 256, GEMM_SMEM>>>(
            a, WH, bb0, bb1, bb2, C, nullptr, ldc);
    };
    auto gemmH = [&](const __half* a, const float* bb, __half* C, bool relu) {
        if (relu)
            gemm_f16<true,true><<<dim3(8, MDIM / BM), 256, GEMM_SMEM>>>(
                a, WH, bb, bb, bb, nullptr, C, DDIM);
        else
            gemm_f16<false,true><<<dim3(8, MDIM / BM), 256, GEMM_SMEM>>>(
                a, WH, bb, bb, bb, nullptr, C, DDIM);
    };

    // ---- encoder ----
    conv_act<true><<<CA_BLK, 256>>>(input_seq, pe, Xq);
    conv_w<<<3 * CW1, 256>>>(enc_wq, enc_wk, enc_wv, WH);
    gemmF(3, Xq, enc_bq, enc_bk, enc_bv, QKV, 3 * DDIM);
    attn_kernel<<<MDIM, 128>>>(QKV, 3 * DDIM, QKV + DDIM, 3 * DDIM, QKV + 2 * DDIM, 3 * DDIM, Aq);
    conv_w<<<CW1, 256>>>(enc_w1, enc_w1, enc_w1, WH);
    gemmH(Aq, enc_b1, Pq, true);
    conv_w<<<CW1, 256>>>(enc_w2, enc_w2, enc_w2, WH);
    gemmH(Pq, enc_b2, Eq, false);                 // enc_out (fp16)

    // ---- decoder self-attn ----
    conv_act<false><<<CA_BLK, 256>>>(output_seq, nullptr, Xq);
    conv_w<<<3 * CW1, 256>>>(dec_s_wq, dec_s_wk, dec_s_wv, WH);
    gemmF(3, Xq, dec_s_bq, dec_s_bk, dec_s_bv, QKV, 3 * DDIM);
    attn_kernel<<<MDIM, 128>>>(QKV, 3 * DDIM, QKV + DDIM, 3 * DDIM, QKV + 2 * DDIM, 3 * DDIM, Aq);

    // ---- decoder cross-attn ----
    conv_w<<<CW1, 256>>>(dec_c_wq, dec_c_wq, dec_c_wq, WH);
    gemmF(1, Aq, dec_c_bq, dec_c_bq, dec_c_bq, T, DDIM);          // Q (fp32)
    conv_w<<<2 * CW1, 256>>>(dec_c_wk, dec_c_wv, dec_c_wv, WH);
    gemmF(2, Eq, dec_c_bk, dec_c_bv, dec_c_bv, KV, 2 * DDIM);     // K,V (fp32)
    attn_kernel<<<MDIM, 128>>>(T, DDIM, KV, 2 * DDIM, KV + DDIM, 2 * DDIM, Aq);

    // ---- decoder FFN + fc ----
    conv_w<<<CW1, 256>>>(dec_w1, dec_w1, dec_w1, WH);
    gemmH(Aq, dec_b1, Pq, true);
    conv_w<<<CW1, 256>>>(dec_w2, dec_w2, dec_w2, WH);
    gemmH(Pq, dec_b2, Xq, false);
    conv_w<<<CW1, 256>>>(fc_w, fc_w, fc_w, WH);
    gemmF(1, Xq, fc_b, fc_b, fc_b, OUT, DDIM);
}

// round 9
// speedup vs baseline: 5.1180x; 1.0172x over previous
#include <cuda_runtime.h>
#include <cuda_fp16.h>
#include <cstdint>

// ---------------------------------------------------------------------------
// DialogueTransformer on GB300 (sm_103a, base sm_103 PTX => legacy mma.sync).
// R9: single-product fp16 HMMA GEMMs; fp16 intermediates everywhere
// (incl. QKV/KV attention inputs); encoder and decoder-self branches run on
// two streams with event fork/join so attn/convert/tail time overlaps MMA.
// ---------------------------------------------------------------------------

#define MDIM 16384
#define DDIM 1024

// fp16 activation buffers
__device__ __align__(256) __half g_q1[MDIM * 3 * DDIM];   // enc QKV
__device__ __align__(256) __half g_q2[MDIM * 3 * DDIM];   // dec-self QKV
__device__ __align__(256) __half g_kvb[MDIM * 2 * DDIM];  // cross K,V
__device__ __align__(256) __half g_cq[MDIM * DDIM];       // cross Q
__device__ __align__(256) __half g_xq[MDIM * DDIM];       // enc input
__device__ __align__(256) __half g_yq[MDIM * DDIM];       // dec input
__device__ __align__(256) __half g_aq[MDIM * DDIM];       // enc attn out
__device__ __align__(256) __half g_sa[MDIM * DDIM];       // dec self-attn out
__device__ __align__(256) __half g_pq[MDIM * DDIM];       // ffn hidden
__device__ __align__(256) __half g_eq[MDIM * DDIM];       // enc_out
__device__ __align__(256) __half g_ca[MDIM * DDIM];       // cross attn out
// fp16 weights (separate per GEMM so streams never collide)
__device__ __align__(256) __half g_w0[3 * DDIM * DDIM];   // enc qkv
__device__ __align__(256) __half g_w1[DDIM * DDIM];       // enc w1
__device__ __align__(256) __half g_w2[DDIM * DDIM];       // enc w2
__device__ __align__(256) __half g_w3[3 * DDIM * DDIM];   // dec self qkv
__device__ __align__(256) __half g_w4[DDIM * DDIM];       // cross q
__device__ __align__(256) __half g_w5[2 * DDIM * DDIM];   // cross k,v
__device__ __align__(256) __half g_w6[DDIM * DDIM];       // dec w1
__device__ __align__(256) __half g_w7[DDIM * DDIM];       // dec w2
__device__ __align__(256) __half g_w8[DDIM * DDIM];       // fc

// ---------------------------------------------------------------------------
// PTX helpers (baseline sm_80+ PTX only)
// ---------------------------------------------------------------------------
__device__ __forceinline__ uint32_t smem_to_u32(const void* p) {
    uint32_t a;
    asm("{ .reg .u64 t; cvta.to.shared.u64 t, %1; cvt.u32.u64 %0, t; }" : "=r"(a) : "l"(p));
    return a;
}
__device__ __forceinline__ void cp_async16(uint32_t saddr, const void* gptr) {
    asm volatile("cp.async.cg.shared.global [%0], [%1], 16;" :: "r"(saddr), "l"(gptr));
}
__device__ __forceinline__ void cp_commit() { asm volatile("cp.async.commit_group;"); }
__device__ __forceinline__ void cp_wait_all() { asm volatile("cp.async.wait_group 0;" ::: "memory"); }

__device__ __forceinline__ void ldsm_x4(uint32_t* r, uint32_t addr) {
    asm volatile("ldmatrix.sync.aligned.m8n8.x4.shared.b16 {%0,%1,%2,%3}, [%4];"
                 : "=r"(r[0]), "=r"(r[1]), "=r"(r[2]), "=r"(r[3]) : "r"(addr));
}
__device__ __forceinline__ void mma16816(float* c, const uint32_t* a,
                                         uint32_t b0, uint32_t b1) {
    asm volatile(
        "mma.sync.aligned.m16n8k16.row.col.f32.f16.f16.f32 "
        "{%0,%1,%2,%3}, {%4,%5,%6,%7}, {%8,%9}, {%0,%1,%2,%3};"
        : "+f"(c[0]), "+f"(c[1]), "+f"(c[2]), "+f"(c[3])
        : "r"(a[0]), "r"(a[1]), "r"(a[2]), "r"(a[3]), "r"(b0), "r"(b1));
}

// ---------------------------------------------------------------------------
// fp16 GEMM: C[m,gn] = sum_k a[m,k]*w[gn,k] + bias(gn)
// BM=128, BN=128, BK=32 halves, 256 thr, 8 warps (2x4 -> 64x32 warp tiles).
// ---------------------------------------------------------------------------
#define BM 128
#define BN 128
#define BK 32
#define NKB (DDIM / BK)   // 32
#define ROWB 80
#define TILE_BYTES (128 * ROWB)          // 10240
#define STAGE_BYTES (2 * TILE_BYTES)     // A, W = 20480
#define GEMM_SMEM (2 * STAGE_BYTES)      // 40960

template <bool RELU, bool F16OUT>
__global__ __launch_bounds__(256, 2)
void gemm_f16(const __half* __restrict__ Ag,
              const __half* __restrict__ Wg,
              const float* __restrict__ b0, const float* __restrict__ b1,
              const float* __restrict__ b2,
              float* __restrict__ Cf, __half* __restrict__ Ch, int ldc) {
    extern __shared__ char smem[];
    const uint32_t sb = smem_to_u32(smem);
    const int tid = threadIdx.x;
    const int wid = tid >> 5;
    const int lane = tid & 31;
    const int bm = blockIdx.y * BM;
    const int gn = blockIdx.x * BN;
    const int wm = (wid & 1) * 64;
    const int wn = (wid >> 1) * 32;

    auto OFF_A = [](int s) { return s * STAGE_BYTES + 0 * TILE_BYTES; };
    auto OFF_W = [](int s) { return s * STAGE_BYTES + 1 * TILE_BYTES; };

    const int fr = tid >> 1;
    const int fc0 = (tid & 1) * 2;
    const __half* gA = Ag + (size_t)(bm + fr) * DDIM;
    const __half* gW = Wg + (size_t)(gn + fr) * DDIM;

    auto fill_stage = [&](int s, int kb) {
        const int k0 = kb * BK;
        const uint32_t srow = fr * ROWB;
#pragma unroll
        for (int i = 0; i < 2; i++) {
            const int c = fc0 + i;
            const uint32_t so = srow + c * 16;
            const int go = k0 + c * 8;
            cp_async16(sb + OFF_A(s) + so, gA + go);
            cp_async16(sb + OFF_W(s) + so, gW + go);
        }
        cp_commit();
    };

    fill_stage(0, 0);
    cp_wait_all();
    __syncthreads();

    float acc[4][4][4];
#pragma unroll
    for (int i = 0; i < 4; i++)
#pragma unroll
        for (int j = 0; j < 4; j++)
#pragma unroll
            for (int q = 0; q < 4; q++) acc[i][j][q] = 0.0f;

    const uint32_t lrow = (lane & 15);
    const uint32_t lcol = (lane >> 4) * 16;

    for (int kb = 0; kb < NKB; kb++) {
        const int s = kb & 1;
        if (kb + 1 < NKB) fill_stage(s ^ 1, kb + 1);

        const uint32_t ab = sb + OFF_A(s) + (wm + lrow) * ROWB + lcol;
        const uint32_t wb = sb + OFF_W(s) + (wn + lrow) * ROWB + lcol;

#pragma unroll
        for (int ks = 0; ks < 2; ks++) {
            const uint32_t ko = ks * 32;
            uint32_t bf[2][4];
#pragma unroll
            for (int p = 0; p < 2; p++)
                ldsm_x4(bf[p], wb + p * (16 * ROWB) + ko);
#pragma unroll
            for (int mt = 0; mt < 4; mt++) {
                uint32_t af[4];
                ldsm_x4(af, ab + mt * (16 * ROWB) + ko);
#pragma unroll
                for (int nt = 0; nt < 4; nt++) {
                    const int p = nt >> 1, o = nt & 1;
                    mma16816(acc[mt][nt], af, bf[p][o], bf[p][o + 2]);
                }
            }
        }
        if (kb + 1 < NKB) cp_wait_all();
        __syncthreads();
    }

    // ---- epilogue ----
    const int g = lane >> 2, t4 = lane & 3;
    const float* bias = (blockIdx.x < 8) ? b0 : ((blockIdx.x < 16) ? b1 : b2);
    const int bb = (blockIdx.x & 7) * BN + wn;

#pragma unroll
    for (int mt = 0; mt < 4; mt++) {
        const int row0 = bm + wm + mt * 16 + g;
#pragma unroll
        for (int nt = 0; nt < 4; nt++) {
            const int col = nt * 8 + 2 * t4;
            const float bx = bias[bb + col];
            const float by = bias[bb + col + 1];
            float2 v0, v1;
            v0.x = acc[mt][nt][0] + bx;
            v0.y = acc[mt][nt][1] + by;
            v1.x = acc[mt][nt][2] + bx;
            v1.y = acc[mt][nt][3] + by;
            if (RELU) {
                v0.x = fmaxf(v0.x, 0.0f); v0.y = fmaxf(v0.y, 0.0f);
                v1.x = fmaxf(v1.x, 0.0f); v1.y = fmaxf(v1.y, 0.0f);
            }
            const size_t o0 = (size_t)row0 * ldc + gn + wn + col;
            if (F16OUT) {
                *(__half2*)(Ch + o0) = __floats2half2_rn(v0.x, v0.y);
                *(__half2*)(Ch + o0 + 8 * (size_t)ldc) = __floats2half2_rn(v1.x, v1.y);
            } else {
                *(float2*)(Cf + o0) = v0;
                *(float2*)(Cf + o0 + 8 * (size_t)ldc) = v1;
            }
        }
    }
}

// ---------------------------------------------------------------------------
// Converters
// ---------------------------------------------------------------------------
template <bool PE>
__global__ __launch_bounds__(256)
void conv_act(const float* __restrict__ x, const float* __restrict__ pe,
              __half* __restrict__ out) {
    const size_t i = ((size_t)blockIdx.x * 256 + threadIdx.x) * 4;
    float4 v = *(const float4*)(x + i);
    if (PE) {
        const int d = (int)(i & (DDIM - 1));
        v.x += pe[d + 0]; v.y += pe[d + 1]; v.z += pe[d + 2]; v.w += pe[d + 3];
    }
    __half2 h01 = __floats2half2_rn(v.x, v.y);
    __half2 h23 = __floats2half2_rn(v.z, v.w);
    *(uint2*)(out + i) = make_uint2(*(uint32_t*)&h01, *(uint32_t*)&h23);
}

__global__ __launch_bounds__(256)
void conv_w(const float* __restrict__ w0, const float* __restrict__ w1,
            const float* __restrict__ w2, __half* __restrict__ WH) {
    const size_t i = ((size_t)blockIdx.x * 256 + threadIdx.x) * 4;
    const int which = (int)(i >> 20);
    const float* src = (which == 0) ? w0 : ((which == 1) ? w1 : w2);
    float4 v = *(const float4*)(src + (i & ((1u << 20) - 1)));
    __half2 h01 = __floats2half2_rn(v.x, v.y);
    __half2 h23 = __floats2half2_rn(v.z, v.w);
    *(uint2*)(WH + i) = make_uint2(*(uint32_t*)&h01, *(uint32_t*)&h23);
}

// ---------------------------------------------------------------------------
// Per-position 8x8 head-mix attention; fp16 strided in, fp16 out.
// ---------------------------------------------------------------------------
#define QROW 132

__global__ __launch_bounds__(128)
void attn_kernel(const __half* __restrict__ Q, int qs,
                 const __half* __restrict__ K, int ks_,
                 const __half* __restrict__ V, int vs,
                 __half* __restrict__ O) {
    __shared__ float sq[8 * QROW + 4];
    __shared__ float sk[8 * QROW + 4];
    __shared__ float sw[64];

    const int p = blockIdx.x;
    const int t = threadIdx.x;
    const __half* Qb = Q + (size_t)p * qs;
    const __half* Kb = K + (size_t)p * ks_;
    const __half* Vb = V + (size_t)p * vs;

    // each thread loads 8 halves (16B) of q and k, converts to fp32 smem
    {
        const int e = t * 8;
        const int i = e >> 7, h = e & 127;
        uint4 rq = *(const uint4*)(Qb + e);
        uint4 rk = *(const uint4*)(Kb + e);
        const __half2* qp = (const __half2*)&rq;
        const __half2* kp = (const __half2*)&rk;
        float* dq = sq + i * QROW + h;
        float* dk = sk + i * QROW + h;
#pragma unroll
        for (int w = 0; w < 4; w++) {
            const float2 fq = __half22float2(qp[w]);
            const float2 fk = __half22float2(kp[w]);
            dq[2 * w] = fq.x; dq[2 * w + 1] = fq.y;
            dk[2 * w] = fk.x; dk[2 * w + 1] = fk.y;
        }
    }
    __syncthreads();

    if (t < 64) {
        const int i = t >> 3, j = t & 7;
        const float* qi = &sq[i * QROW];
        const float* kj = &sk[j * QROW];
        float s = 0.0f;
#pragma unroll
        for (int h = 0; h < 128; h += 4) {
            const float4 a = *(const float4*)(qi + h);
            const float4 b = *(const float4*)(kj + h);
            s += a.x * b.x + a.y * b.y + a.z * b.z + a.w * b.w;
        }
        sw[t] = s * 0.08838834764831845f;
    }
    __syncthreads();

    if (t < 8) {
        float m = sw[t * 8];
#pragma unroll
        for (int j = 1; j < 8; j++) m = fmaxf(m, sw[t * 8 + j]);
        float s = 0.0f;
        float e[8];
#pragma unroll
        for (int j = 0; j < 8; j++) { e[j] = __expf(sw[t * 8 + j] - m); s += e[j]; }
        const float inv = 1.0f / s;
#pragma unroll
        for (int j = 0; j < 8; j++) sw[t * 8 + j] = e[j] * inv;
    }
    __syncthreads();

    float vj[8];
#pragma unroll
    for (int j = 0; j < 8; j++) vj[j] = __half2float(Vb[j * 128 + t]);
    const size_t obase = (size_t)p * 1024;
#pragma unroll
    for (int i = 0; i < 8; i++) {
        float o = 0.0f;
#pragma unroll
        for (int j = 0; j < 8; j++) o += sw[i * 8 + j] * vj[j];
        O[obase + i * 128 + t] = __float2half_rn(o);
    }
}

// ---------------------------------------------------------------------------
// Launch — two streams: s0 = default (encoder + tail), s1 = decoder-self.
// Stream/events are created once (host resources, not device memory); the
// launched work is identical on every call.
// ---------------------------------------------------------------------------
extern "C" void kernel_launch(void* const* d_in, const int* in_sizes, int n_in,
                              void* d_out, int out_size) {
    const float* input_seq  = (const float*)d_in[0];
    const float* output_seq = (const float*)d_in[1];
    const float* pe         = (const float*)d_in[2];
    const float* enc_wq = (const float*)d_in[3];   const float* enc_bq = (const float*)d_in[4];
    const float* enc_wk = (const float*)d_in[5];   const float* enc_bk = (const float*)d_in[6];
    const float* enc_wv = (const float*)d_in[7];   const float* enc_bv = (const float*)d_in[8];
    const float* enc_w1 = (const float*)d_in[9];   const float* enc_b1 = (const float*)d_in[10];
    const float* enc_w2 = (const float*)d_in[11];  const float* enc_b2 = (const float*)d_in[12];
    const float* dec_s_wq = (const float*)d_in[13]; const float* dec_s_bq = (const float*)d_in[14];
    const float* dec_s_wk = (const float*)d_in[15]; const float* dec_s_bk = (const float*)d_in[16];
    const float* dec_s_wv = (const float*)d_in[17]; const float* dec_s_bv = (const float*)d_in[18];
    const float* dec_c_wq = (const float*)d_in[19]; const float* dec_c_bq = (const float*)d_in[20];
    const float* dec_c_wk = (const float*)d_in[21]; const float* dec_c_bk = (const float*)d_in[22];
    const float* dec_c_wv = (const float*)d_in[23]; const float* dec_c_bv = (const float*)d_in[24];
    const float* dec_w1 = (const float*)d_in[25];  const float* dec_b1 = (const float*)d_in[26];
    const float* dec_w2 = (const float*)d_in[27];  const float* dec_b2 = (const float*)d_in[28];
    const float* fc_w   = (const float*)d_in[29];  const float* fc_b   = (const float*)d_in[30];

    __half *Q1, *Q2, *KVb, *Cq, *Xq, *Yq, *Aq, *Sa, *Pq, *Eq, *Ca;
    __half *W0, *W1, *W2, *W3, *W4, *W5, *W6, *W7, *W8;
    cudaGetSymbolAddress((void**)&Q1, g_q1);
    cudaGetSymbolAddress((void**)&Q2, g_q2);
    cudaGetSymbolAddress((void**)&KVb, g_kvb);
    cudaGetSymbolAddress((void**)&Cq, g_cq);
    cudaGetSymbolAddress((void**)&Xq, g_xq);
    cudaGetSymbolAddress((void**)&Yq, g_yq);
    cudaGetSymbolAddress((void**)&Aq, g_aq);
    cudaGetSymbolAddress((void**)&Sa, g_sa);
    cudaGetSymbolAddress((void**)&Pq, g_pq);
    cudaGetSymbolAddress((void**)&Eq, g_eq);
    cudaGetSymbolAddress((void**)&Ca, g_ca);
    cudaGetSymbolAddress((void**)&W0, g_w0);
    cudaGetSymbolAddress((void**)&W1, g_w1);
    cudaGetSymbolAddress((void**)&W2, g_w2);
    cudaGetSymbolAddress((void**)&W3, g_w3);
    cudaGetSymbolAddress((void**)&W4, g_w4);
    cudaGetSymbolAddress((void**)&W5, g_w5);
    cudaGetSymbolAddress((void**)&W6, g_w6);
    cudaGetSymbolAddress((void**)&W7, g_w7);
    cudaGetSymbolAddress((void**)&W8, g_w8);
    float* OUT = (float*)d_out;

    cudaFuncSetAttribute(gemm_f16<false,false>, cudaFuncAttributeMaxDynamicSharedMemorySize, GEMM_SMEM);
    cudaFuncSetAttribute(gemm_f16<false,true>,  cudaFuncAttributeMaxDynamicSharedMemorySize, GEMM_SMEM);
    cudaFuncSetAttribute(gemm_f16<true,true>,   cudaFuncAttributeMaxDynamicSharedMemorySize, GEMM_SMEM);

    // one-time host resources (reused; work per call is identical)
    static cudaStream_t s1 = nullptr;
    static cudaEvent_t evFork = nullptr, evJoin = nullptr;
    if (!s1) {
        cudaStreamCreateWithFlags(&s1, cudaStreamNonBlocking);
        cudaEventCreateWithFlags(&evFork, cudaEventDisableTiming);
        cudaEventCreateWithFlags(&evJoin, cudaEventDisableTiming);
    }

    const int CA_BLK = MDIM * DDIM / (4 * 256);   // 16384
    const int CW1 = DDIM * DDIM / (4 * 256);      // 1024

    auto gemmH16 = [&](cudaStream_t st, int ng, const __half* a, const __half* w,
                       const float* bb0, const float* bb1, const float* bb2,
                       __half* C, int ldc, bool relu) {
        if (relu)
            gemm_f16<true,true><<<dim3(ng * 8, MDIM / BM), 256, GEMM_SMEM, st>>>(
                a, w, bb0, bb1, bb2, nullptr, C, ldc);
        else
            gemm_f16<false,true><<<dim3(ng * 8, MDIM / BM), 256, GEMM_SMEM, st>>>(
                a, w, bb0, bb1, bb2, nullptr, C, ldc);
    };

    // ---- fork ----
    cudaEventRecord(evFork, 0);
    cudaStreamWaitEvent(s1, evFork, 0);

    // ========== stream s1: decoder-self branch through cross-Q ==========
    conv_act<false><<<CA_BLK, 256, 0, s1>>>(output_seq, nullptr, Yq);
    conv_w<<<3 * CW1, 256, 0, s1>>>(dec_s_wq, dec_s_wk, dec_s_wv, W3);
    gemmH16(s1, 3, Yq, W3, dec_s_bq, dec_s_bk, dec_s_bv, Q2, 3 * DDIM, false);
    attn_kernel<<<MDIM, 128, 0, s1>>>(Q2, 3 * DDIM, Q2 + DDIM, 3 * DDIM,
                                      Q2 + 2 * DDIM, 3 * DDIM, Sa);
    conv_w<<<CW1, 256, 0, s1>>>(dec_c_wq, dec_c_wq, dec_c_wq, W4);
    gemmH16(s1, 1, Sa, W4, dec_c_bq, dec_c_bq, dec_c_bq, Cq, DDIM, false);
    cudaEventRecord(evJoin, s1);

    // ========== stream 0: encoder branch ==========
    conv_w<<<3 * CW1, 256>>>(enc_wq, enc_wk, enc_wv, W0);
    conv_act<true><<<CA_BLK, 256>>>(input_seq, pe, Xq);
    gemmH16(0, 3, Xq, W0, enc_bq, enc_bk, enc_bv, Q1, 3 * DDIM, false);
    attn_kernel<<<MDIM, 128>>>(Q1, 3 * DDIM, Q1 + DDIM, 3 * DDIM,
                               Q1 + 2 * DDIM, 3 * DDIM, Aq);
    conv_w<<<CW1, 256>>>(enc_w1, enc_w1, enc_w1, W1);
    gemmH16(0, 1, Aq, W1, enc_b1, enc_b1, enc_b1, Pq, DDIM, true);
    conv_w<<<CW1, 256>>>(enc_w2, enc_w2, enc_w2, W2);
    gemmH16(0, 1, Pq, W2, enc_b2, enc_b2, enc_b2, Eq, DDIM, false);
    conv_w<<<2 * CW1, 256>>>(dec_c_wk, dec_c_wv, dec_c_wv, W5);
    gemmH16(0, 2, Eq, W5, dec_c_bk, dec_c_bv, dec_c_bv, KVb, 2 * DDIM, false);

    // ---- join ----
    cudaStreamWaitEvent(0, evJoin, 0);

    // ========== stream 0: cross-attn + decoder FFN + fc ==========
    attn_kernel<<<MDIM, 128>>>(Cq, DDIM, KVb, 2 * DDIM, KVb + DDIM, 2 * DDIM, Ca);
    conv_w<<<CW1, 256>>>(dec_w1, dec_w1, dec_w1, W6);
    gemmH16(0, 1, Ca, W6, dec_b1, dec_b1, dec_b1, Pq, DDIM, true);
    conv_w<<<CW1, 256>>>(dec_w2, dec_w2, dec_w2, W7);
    gemmH16(0, 1, Pq, W7, dec_b2, dec_b2, dec_b2, Xq, DDIM, false);
    conv_w<<<CW1, 256>>>(fc_w, fc_w, fc_w, W8);
    gemm_f16<false,false><<<dim3(8, MDIM / BM), 256, GEMM_SMEM>>>(
        Xq, W8, fc_b, fc_b, fc_b, OUT, nullptr, DDIM);
}